// round 2
// baseline (speedup 1.0000x reference)
#include <cuda_runtime.h>
#include <cstdint>

// Problem constants (fixed by the reference)
#define Bb 2
#define Tt 2048
#define Cc 1024
#define Hh 16
#define Dd 64
#define Pp 2048
#define C3 3072

// Scratch (device globals — no runtime allocation allowed)
__device__ float g_qkv[(size_t)Bb * Tt * C3];   // [B*T, 3C]
__device__ float g_y[(size_t)Bb * Tt * Cc];     // [B*T, C] attention output

// ---------------------------------------------------------------------------
// Tiled FP32 GEMM: C = A[M,K] @ B[K,N], row-major, all dims multiples of 128/16
// BM=BN=128, BK=16, 256 threads, 8x8 per thread.
// ---------------------------------------------------------------------------
__global__ __launch_bounds__(256, 2)
void sgemm_kernel(const float* __restrict__ A, const float* __restrict__ Bm,
                  float* __restrict__ Cm, int M, int N, int K)
{
    __shared__ float As[16][132];   // A tile transposed: As[k][m], padded pitch
    __shared__ float Bs[16][128];   // B tile natural:     Bs[k][n]

    const int tid = threadIdx.x;
    const int tx = tid & 15, ty = tid >> 4;
    const int bm = blockIdx.y * 128, bn = blockIdx.x * 128;

    const int a_row = tid >> 2;          // 0..63
    const int a_col = (tid & 3) << 2;    // 0,4,8,12
    const int b_row = tid >> 5;          // 0..7
    const int b_col = (tid & 31) << 2;   // 0..124

    float acc[8][8];
    #pragma unroll
    for (int i = 0; i < 8; i++)
        #pragma unroll
        for (int j = 0; j < 8; j++) acc[i][j] = 0.f;

    for (int k0 = 0; k0 < K; k0 += 16) {
        #pragma unroll
        for (int r = 0; r < 2; r++) {
            float4 av = *(const float4*)&A[(size_t)(bm + a_row + r*64)*K + k0 + a_col];
            As[a_col+0][a_row + r*64] = av.x;
            As[a_col+1][a_row + r*64] = av.y;
            As[a_col+2][a_row + r*64] = av.z;
            As[a_col+3][a_row + r*64] = av.w;
        }
        #pragma unroll
        for (int r = 0; r < 2; r++) {
            *(float4*)&Bs[b_row + r*8][b_col] =
                *(const float4*)&Bm[(size_t)(k0 + b_row + r*8)*N + bn + b_col];
        }
        __syncthreads();

        #pragma unroll
        for (int k = 0; k < 16; k++) {
            float a[8], bv[8];
            *(float4*)&a[0]  = *(const float4*)&As[k][ty*8];
            *(float4*)&a[4]  = *(const float4*)&As[k][ty*8 + 4];
            *(float4*)&bv[0] = *(const float4*)&Bs[k][tx*8];
            *(float4*)&bv[4] = *(const float4*)&Bs[k][tx*8 + 4];
            #pragma unroll
            for (int i = 0; i < 8; i++)
                #pragma unroll
                for (int j = 0; j < 8; j++)
                    acc[i][j] = fmaf(a[i], bv[j], acc[i][j]);
        }
        __syncthreads();
    }

    #pragma unroll
    for (int i = 0; i < 8; i++) {
        float4 v0 = make_float4(acc[i][0], acc[i][1], acc[i][2], acc[i][3]);
        float4 v1 = make_float4(acc[i][4], acc[i][5], acc[i][6], acc[i][7]);
        size_t row = (size_t)(bm + ty*8 + i);
        *(float4*)&Cm[row*N + bn + tx*8]     = v0;
        *(float4*)&Cm[row*N + bn + tx*8 + 4] = v1;
    }
}

// ---------------------------------------------------------------------------
// Flash attention over [prefix cache (P) + causal self (T)] keys.
// One block = one (b, h, 64-query tile). 256 threads = 16x16 grid, 4x4 micro.
// smem: sQt[d][r] (Q transposed, pre-scaled), sKP (K^T tile, reused as P tile),
//       sV[k][d]. Pitch 68 floats (16B-aligned, conflict-free access patterns).
// ---------------------------------------------------------------------------
#define FP 68

__global__ __launch_bounds__(256)
void flash_kernel(const float* __restrict__ qkv,
                  const float* __restrict__ cache_k,
                  const float* __restrict__ cache_v,
                  float* __restrict__ y)
{
    extern __shared__ float sm[];
    float* sQt = sm;               // [64][FP]  sQt[d*FP + r]
    float* sKP = sm + 64*FP;       // [64][FP]  K^T: [d][c]  /  P: [r][c]
    float* sV  = sm + 2*64*FP;     // [64][FP]  sV[k*FP + d]

    const int tid = threadIdx.x;
    const int tx = tid & 15, ty = tid >> 4;
    const int tx4 = tx * 4, ty4 = ty * 4;
    const int qt = blockIdx.x, h = blockIdx.y, b = blockIdx.z;
    const int q0 = qt * 64;

    const int lr = tid >> 2;       // loader row 0..63
    const int lq = tid & 3;        // loader quad 0..3

    // Load Q tile (transposed + pre-scaled by 1/sqrt(D))
    {
        const float* qr = qkv + ((size_t)(b*Tt + q0 + lr))*C3 + h*Dd;
        #pragma unroll
        for (int u = 0; u < 4; u++) {
            int d4 = (lq + 4*u) * 4;
            float4 v = *(const float4*)&qr[d4];
            sQt[(d4+0)*FP + lr] = v.x * 0.125f;
            sQt[(d4+1)*FP + lr] = v.y * 0.125f;
            sQt[(d4+2)*FP + lr] = v.z * 0.125f;
            sQt[(d4+3)*FP + lr] = v.w * 0.125f;
        }
    }

    float O[4][4];
    float m_i[4], l_i[4];
    #pragma unroll
    for (int i = 0; i < 4; i++) {
        m_i[i] = -1e30f; l_i[i] = 0.f;
        #pragma unroll
        for (int j = 0; j < 4; j++) O[i][j] = 0.f;
    }

    const int nPrefix = Pp / 64;          // 32
    const int nBlk = nPrefix + qt + 1;    // prefix + causal self tiles

    for (int jb = 0; jb < nBlk; jb++) {
        __syncthreads();   // previous P/V reads complete (and Q visible on jb=0)

        // Load K tile (transposed) and V tile (natural)
        const float* kr; const float* vr;
        if (jb < nPrefix) {
            size_t base = ((size_t)(b*Hh + h)*Pp + jb*64 + lr) * Dd;
            kr = cache_k + base;
            vr = cache_v + base;
        } else {
            size_t base = ((size_t)(b*Tt + (jb - nPrefix)*64 + lr))*C3 + h*Dd;
            kr = qkv + base + Cc;
            vr = qkv + base + 2*Cc;
        }
        #pragma unroll
        for (int u = 0; u < 4; u++) {
            int d4 = (lq + 4*u) * 4;
            float4 kv = *(const float4*)&kr[d4];
            sKP[(d4+0)*FP + lr] = kv.x;
            sKP[(d4+1)*FP + lr] = kv.y;
            sKP[(d4+2)*FP + lr] = kv.z;
            sKP[(d4+3)*FP + lr] = kv.w;
            *(float4*)&sV[lr*FP + d4] = *(const float4*)&vr[d4];
        }
        __syncthreads();

        // S = Q K^T  (Q pre-scaled)
        float S[4][4];
        #pragma unroll
        for (int i = 0; i < 4; i++)
            #pragma unroll
            for (int j = 0; j < 4; j++) S[i][j] = 0.f;

        #pragma unroll 8
        for (int d = 0; d < 64; d++) {
            float4 qv = *(const float4*)&sQt[d*FP + ty4];
            float4 kv = *(const float4*)&sKP[d*FP + tx4];
            float qa[4] = {qv.x, qv.y, qv.z, qv.w};
            float ka[4] = {kv.x, kv.y, kv.z, kv.w};
            #pragma unroll
            for (int i = 0; i < 4; i++)
                #pragma unroll
                for (int j = 0; j < 4; j++)
                    S[i][j] = fmaf(qa[i], ka[j], S[i][j]);
        }

        // Causal mask on the diagonal self tile only
        if (jb == nBlk - 1) {
            #pragma unroll
            for (int i = 0; i < 4; i++)
                #pragma unroll
                for (int j = 0; j < 4; j++)
                    if (tx4 + j > ty4 + i) S[i][j] = -1e30f;
        }

        // Online softmax (row reductions across the 16 tx lanes via shfl)
        float alpha[4];
        #pragma unroll
        for (int i = 0; i < 4; i++) {
            float rm = fmaxf(fmaxf(S[i][0], S[i][1]), fmaxf(S[i][2], S[i][3]));
            #pragma unroll
            for (int msk = 1; msk < 16; msk <<= 1)
                rm = fmaxf(rm, __shfl_xor_sync(0xffffffffu, rm, msk));
            float mn = fmaxf(m_i[i], rm);
            alpha[i] = __expf(m_i[i] - mn);
            float rs = 0.f;
            #pragma unroll
            for (int j = 0; j < 4; j++) {
                float p = __expf(S[i][j] - mn);
                S[i][j] = p;
                rs += p;
            }
            #pragma unroll
            for (int msk = 1; msk < 16; msk <<= 1)
                rs += __shfl_xor_sync(0xffffffffu, rs, msk);
            l_i[i] = l_i[i] * alpha[i] + rs;
            m_i[i] = mn;
            #pragma unroll
            for (int j = 0; j < 4; j++) O[i][j] *= alpha[i];
        }

        __syncthreads();   // all threads done reading sKP as K^T

        // Store P naturally: sKP[r][c]  (STS.128, conflict-free)
        #pragma unroll
        for (int i = 0; i < 4; i++)
            *(float4*)&sKP[(ty4+i)*FP + tx4] =
                make_float4(S[i][0], S[i][1], S[i][2], S[i][3]);
        __syncthreads();

        // O += P @ V
        #pragma unroll 8
        for (int kk = 0; kk < 64; kk++) {
            float4 vv = *(const float4*)&sV[kk*FP + tx4];
            float va[4] = {vv.x, vv.y, vv.z, vv.w};
            float pa[4];
            #pragma unroll
            for (int i = 0; i < 4; i++) pa[i] = sKP[(ty4+i)*FP + kk];
            #pragma unroll
            for (int i = 0; i < 4; i++)
                #pragma unroll
                for (int j = 0; j < 4; j++)
                    O[i][j] = fmaf(pa[i], va[j], O[i][j]);
        }
    }

    // Normalize and write y in [B, T, H*D] layout (ready for proj GEMM)
    #pragma unroll
    for (int i = 0; i < 4; i++) {
        float inv = 1.f / l_i[i];
        float4 o = make_float4(O[i][0]*inv, O[i][1]*inv, O[i][2]*inv, O[i][3]*inv);
        *(float4*)&y[((size_t)(b*Tt + q0 + ty4 + i))*Cc + h*Dd + tx4] = o;
    }
}

// ---------------------------------------------------------------------------
// Launch
// ---------------------------------------------------------------------------
extern "C" void kernel_launch(void* const* d_in, const int* in_sizes, int n_in,
                              void* d_out, int out_size)
{
    const float* x       = (const float*)d_in[0];
    const float* W_attn  = (const float*)d_in[1];
    const float* W_proj  = (const float*)d_in[2];
    const float* cache_k = (const float*)d_in[3];
    const float* cache_v = (const float*)d_in[4];
    float* out = (float*)d_out;

    float *qkv_p = nullptr, *y_p = nullptr;
    cudaGetSymbolAddress((void**)&qkv_p, g_qkv);
    cudaGetSymbolAddress((void**)&y_p, g_y);

    const int smem_flash = 3 * 64 * FP * (int)sizeof(float);   // 52224 B
    cudaFuncSetAttribute(flash_kernel,
                         cudaFuncAttributeMaxDynamicSharedMemorySize, smem_flash);

    dim3 blk(256);
    // 1) qkv = x @ W_attn : [4096, 3072]
    sgemm_kernel<<<dim3(C3/128, (Bb*Tt)/128), blk>>>(x, W_attn, qkv_p,
                                                     Bb*Tt, C3, Cc);
    // 2) flash attention over prefix + causal self
    flash_kernel<<<dim3(Tt/64, Hh, Bb), blk, smem_flash>>>(qkv_p, cache_k,
                                                           cache_v, y_p);
    // 3) out = y @ W_proj : [4096, 1024]
    sgemm_kernel<<<dim3(Cc/128, (Bb*Tt)/128), blk>>>(y_p, W_proj, out,
                                                     Bb*Tt, Cc, Cc);
}

// round 5
// speedup vs baseline: 1.2735x; 1.2735x over previous
#include <cuda_runtime.h>
#include <cuda_bf16.h>
#include <cstdint>

// Problem constants (fixed by the reference)
#define Bb 2
#define Tt 2048
#define Cc 1024
#define Hh 16
#define Dd 64
#define Pp 2048
#define C3 3072
#define MM (Bb*Tt)   // 4096 rows

// ---------------------------------------------------------------------------
// Scratch (device globals — no runtime allocation allowed)
// ---------------------------------------------------------------------------
__device__ float g_qkv[(size_t)MM * C3];                 // [B*T, 3C]
__device__ float g_y[(size_t)MM * Cc];                   // [B*T, C]
__device__ __nv_bfloat16 g_xhi[(size_t)MM * Cc];
__device__ __nv_bfloat16 g_xlo[(size_t)MM * Cc];
__device__ __nv_bfloat16 g_yhi[(size_t)MM * Cc];
__device__ __nv_bfloat16 g_ylo[(size_t)MM * Cc];
__device__ __nv_bfloat16 g_wahi[(size_t)C3 * Cc];        // W_attn^T [3072][1024]
__device__ __nv_bfloat16 g_walo[(size_t)C3 * Cc];
__device__ __nv_bfloat16 g_wphi[(size_t)Cc * Cc];        // W_proj^T [1024][1024]
__device__ __nv_bfloat16 g_wplo[(size_t)Cc * Cc];

// ---------------------------------------------------------------------------
// PTX helpers: mma.sync / ldmatrix / cp.async (all valid on plain sm_103)
// ---------------------------------------------------------------------------
__device__ __forceinline__ uint32_t smem_u32(const void* p) {
    uint32_t a;
    asm("{ .reg .u64 t; cvta.to.shared.u64 t, %1; cvt.u32.u64 %0, t; }"
        : "=r"(a) : "l"(p));
    return a;
}
__device__ __forceinline__ void ldsm_x4(uint32_t* r, uint32_t addr) {
    asm volatile("ldmatrix.sync.aligned.m8n8.x4.shared.b16 {%0,%1,%2,%3}, [%4];"
        : "=r"(r[0]), "=r"(r[1]), "=r"(r[2]), "=r"(r[3]) : "r"(addr));
}
__device__ __forceinline__ void mma16816(float* d, const uint32_t* a,
                                         uint32_t b0, uint32_t b1) {
    asm volatile(
        "mma.sync.aligned.m16n8k16.row.col.f32.bf16.bf16.f32 "
        "{%0,%1,%2,%3}, {%4,%5,%6,%7}, {%8,%9}, {%0,%1,%2,%3};"
        : "+f"(d[0]), "+f"(d[1]), "+f"(d[2]), "+f"(d[3])
        : "r"(a[0]), "r"(a[1]), "r"(a[2]), "r"(a[3]), "r"(b0), "r"(b1));
}
__device__ __forceinline__ void cp16(uint32_t dst, const void* src) {
    asm volatile("cp.async.cg.shared.global [%0], [%1], 16;"
                 :: "r"(dst), "l"(src) : "memory");
}
#define CP_COMMIT() asm volatile("cp.async.commit_group;" ::: "memory")
#define CP_WAIT(n)  asm volatile("cp.async.wait_group %0;" :: "n"(n) : "memory")

// ---------------------------------------------------------------------------
// fp32 -> (bf16 hi, bf16 lo) split, elementwise (x and y activations)
// ---------------------------------------------------------------------------
struct alignas(8) bf16x4 { __nv_bfloat16 a, b, c, d; };

__global__ __launch_bounds__(256)
void split_kernel(const float* __restrict__ in, __nv_bfloat16* __restrict__ hi,
                  __nv_bfloat16* __restrict__ lo, int n4)
{
    int i = blockIdx.x * blockDim.x + threadIdx.x;
    if (i >= n4) return;
    float4 v = ((const float4*)in)[i];
    __nv_bfloat16 h0 = __float2bfloat16_rn(v.x);
    __nv_bfloat16 h1 = __float2bfloat16_rn(v.y);
    __nv_bfloat16 h2 = __float2bfloat16_rn(v.z);
    __nv_bfloat16 h3 = __float2bfloat16_rn(v.w);
    __nv_bfloat16 l0 = __float2bfloat16_rn(v.x - __bfloat162float(h0));
    __nv_bfloat16 l1 = __float2bfloat16_rn(v.y - __bfloat162float(h1));
    __nv_bfloat16 l2 = __float2bfloat16_rn(v.z - __bfloat162float(h2));
    __nv_bfloat16 l3 = __float2bfloat16_rn(v.w - __bfloat162float(h3));
    ((bf16x4*)hi)[i] = bf16x4{h0, h1, h2, h3};
    ((bf16x4*)lo)[i] = bf16x4{l0, l1, l2, l3};
}

// ---------------------------------------------------------------------------
// W [KW,NW] fp32 -> transposed bf16 hi/lo [NW,KW] (K-major)
// ---------------------------------------------------------------------------
__global__ __launch_bounds__(256)
void wsplit_t_kernel(const float* __restrict__ W, __nv_bfloat16* __restrict__ hi,
                     __nv_bfloat16* __restrict__ lo, int KW, int NW)
{
    __shared__ float t[32][33];
    const int n0 = blockIdx.x * 32, k0 = blockIdx.y * 32;
    const int tx = threadIdx.x, ty = threadIdx.y;
    #pragma unroll
    for (int r = 0; r < 4; r++)
        t[ty + 8*r][tx] = W[(size_t)(k0 + ty + 8*r) * NW + n0 + tx];
    __syncthreads();
    #pragma unroll
    for (int r = 0; r < 4; r++) {
        int n = ty + 8*r;
        float v = t[tx][n];
        __nv_bfloat16 h = __float2bfloat16_rn(v);
        __nv_bfloat16 l = __float2bfloat16_rn(v - __bfloat162float(h));
        size_t o = (size_t)(n0 + n) * KW + k0 + tx;
        hi[o] = h;
        lo[o] = l;
    }
}

// ---------------------------------------------------------------------------
// Tensor-core GEMM (mma.sync bf16-split):
//   C[M,N] = (Ahi+Alo)[M,K] @ (Bhi+Blo)[N,K]^T   (fp32 out)
// CTA tile 128x128, BK=64, 8 warps (2m x 4n), warp tile 64x32.
// Smem per stage: 4 planes (Ahi/Alo/Bhi/Blo) of 128 rows x 128 B, XOR-swizzled.
// ---------------------------------------------------------------------------
#define PLANE 16384
#define STAGE (4 * PLANE)
#define GEMM_SMEM (2 * STAGE)    // 131072 B

__device__ __forceinline__ void load_stage(
    const __nv_bfloat16* __restrict__ Ahi, const __nv_bfloat16* __restrict__ Alo,
    const __nv_bfloat16* __restrict__ Bhi, const __nv_bfloat16* __restrict__ Blo,
    int bm, int bn, int K, int kt, uint32_t so, int tid)
{
    const __nv_bfloat16* srcs[4] = {Ahi, Alo, Bhi, Blo};
    #pragma unroll
    for (int p = 0; p < 4; p++) {
        const __nv_bfloat16* src = srcs[p];
        const int rb = (p < 2) ? bm : bn;
        #pragma unroll
        for (int i = 0; i < 4; i++) {
            int idx = i * 256 + tid;
            int row = idx >> 3, c = idx & 7;
            uint32_t dst = so + p * PLANE + row * 128 + ((c ^ (row & 7)) << 4);
            cp16(dst, src + (size_t)(rb + row) * K + kt * 64 + c * 8);
        }
    }
}

__global__ __launch_bounds__(256, 1)
void gemm_mma(const __nv_bfloat16* __restrict__ Ahi, const __nv_bfloat16* __restrict__ Alo,
              const __nv_bfloat16* __restrict__ Bhi, const __nv_bfloat16* __restrict__ Blo,
              float* __restrict__ Cm, int M, int N, int K)
{
    extern __shared__ char smem[];
    const uint32_t sb = smem_u32(smem);
    const int tid = threadIdx.x;
    const int wid = tid >> 5, lane = tid & 31;
    const int bn = blockIdx.x * 128, bm = blockIdx.y * 128;
    const int m0 = (wid >> 2) * 64;      // warp row origin (0 or 64)
    const int n0 = (wid & 3) * 32;       // warp col origin

    float acc[4][4][4];
    #pragma unroll
    for (int mt = 0; mt < 4; mt++)
        #pragma unroll
        for (int nt = 0; nt < 4; nt++)
            #pragma unroll
            for (int j = 0; j < 4; j++) acc[mt][nt][j] = 0.f;

    const int KT = K / 64;
    load_stage(Ahi, Alo, Bhi, Blo, bm, bn, K, 0, sb, tid);
    CP_COMMIT();

    // ldmatrix lane address components (same pattern for A and B, non-trans:
    // lanes 0-7 -> mat0 (rows 0-7, k-chunk 0), 8-15 -> mat1, 16-23 -> mat2, 24-31 -> mat3)
    const int a_rh = (lane >> 3) & 1;    // A: row half (mat&1)
    const int a_kh = lane >> 4;          // A: k-chunk half (mat>>1)
    const int b_nh = lane >> 4;          // B: n half (mat>>1)
    const int b_kh = (lane >> 3) & 1;    // B: k-chunk half (mat&1)
    const int l7 = lane & 7;

    for (int kt = 0; kt < KT; kt++) {
        const int s = kt & 1;
        if (kt + 1 < KT) {
            load_stage(Ahi, Alo, Bhi, Blo, bm, bn, K, kt + 1, sb + (s ^ 1) * STAGE, tid);
            CP_COMMIT();
            CP_WAIT(1);
        } else {
            CP_WAIT(0);
        }
        __syncthreads();

        const uint32_t Ah = sb + s * STAGE;
        const uint32_t Al = Ah + PLANE;
        const uint32_t Bh = Ah + 2 * PLANE;
        const uint32_t Bl = Ah + 3 * PLANE;

        #pragma unroll
        for (int ks = 0; ks < 4; ks++) {
            uint32_t ah[4][4], al[4][4], bh[4][2], bl[4][2];
            #pragma unroll
            for (int mt = 0; mt < 4; mt++) {
                int r = m0 + mt * 16 + a_rh * 8 + l7;
                int kc = ks * 2 + a_kh;
                uint32_t off = (uint32_t)(r * 128 + ((kc ^ (r & 7)) << 4));
                ldsm_x4(ah[mt], Ah + off);
                ldsm_x4(al[mt], Al + off);
            }
            #pragma unroll
            for (int nt2 = 0; nt2 < 2; nt2++) {
                int rn = n0 + nt2 * 16 + b_nh * 8 + l7;
                int kc = ks * 2 + b_kh;
                uint32_t off = (uint32_t)(rn * 128 + ((kc ^ (rn & 7)) << 4));
                uint32_t t0[4], t1[4];
                ldsm_x4(t0, Bh + off);     // NON-trans: [n][k] smem IS col-major KxN
                ldsm_x4(t1, Bl + off);
                bh[nt2*2][0] = t0[0]; bh[nt2*2][1] = t0[1];
                bh[nt2*2+1][0] = t0[2]; bh[nt2*2+1][1] = t0[3];
                bl[nt2*2][0] = t1[0]; bl[nt2*2][1] = t1[1];
                bl[nt2*2+1][0] = t1[2]; bl[nt2*2+1][1] = t1[3];
            }
            #pragma unroll
            for (int mt = 0; mt < 4; mt++)
                #pragma unroll
                for (int nt = 0; nt < 4; nt++) {
                    mma16816(acc[mt][nt], ah[mt], bh[nt][0], bh[nt][1]);
                    mma16816(acc[mt][nt], ah[mt], bl[nt][0], bl[nt][1]);
                    mma16816(acc[mt][nt], al[mt], bh[nt][0], bh[nt][1]);
                }
        }
        __syncthreads();
    }

    // Epilogue: fragment layout — d0,d1 at (g, q*2), d2,d3 at (g+8, q*2)
    const int g = lane >> 2, q = lane & 3;
    #pragma unroll
    for (int mt = 0; mt < 4; mt++) {
        #pragma unroll
        for (int nt = 0; nt < 4; nt++) {
            size_t row = (size_t)(bm + m0 + mt * 16 + g);
            size_t col = (size_t)(bn + n0 + nt * 8 + q * 2);
            *(float2*)&Cm[row * N + col] = make_float2(acc[mt][nt][0], acc[mt][nt][1]);
            *(float2*)&Cm[(row + 8) * N + col] = make_float2(acc[mt][nt][2], acc[mt][nt][3]);
        }
    }
}

// ---------------------------------------------------------------------------
// Flash attention over [prefix cache (P) + causal self (T)] keys. (unchanged)
// ---------------------------------------------------------------------------
#define FP 68

__global__ __launch_bounds__(256)
void flash_kernel(const float* __restrict__ qkv,
                  const float* __restrict__ cache_k,
                  const float* __restrict__ cache_v,
                  float* __restrict__ y)
{
    extern __shared__ float sm[];
    float* sQt = sm;               // [64][FP]  sQt[d*FP + r]
    float* sKP = sm + 64*FP;       // [64][FP]  K^T: [d][c]  /  P: [r][c]
    float* sV  = sm + 2*64*FP;     // [64][FP]  sV[k*FP + d]

    const int tid = threadIdx.x;
    const int tx = tid & 15, ty = tid >> 4;
    const int tx4 = tx * 4, ty4 = ty * 4;
    const int qt = blockIdx.x, h = blockIdx.y, b = blockIdx.z;
    const int q0 = qt * 64;

    const int lr = tid >> 2;
    const int lq = tid & 3;

    {
        const float* qr = qkv + ((size_t)(b*Tt + q0 + lr))*C3 + h*Dd;
        #pragma unroll
        for (int u = 0; u < 4; u++) {
            int d4 = (lq + 4*u) * 4;
            float4 v = *(const float4*)&qr[d4];
            sQt[(d4+0)*FP + lr] = v.x * 0.125f;
            sQt[(d4+1)*FP + lr] = v.y * 0.125f;
            sQt[(d4+2)*FP + lr] = v.z * 0.125f;
            sQt[(d4+3)*FP + lr] = v.w * 0.125f;
        }
    }

    float O[4][4];
    float m_i[4], l_i[4];
    #pragma unroll
    for (int i = 0; i < 4; i++) {
        m_i[i] = -1e30f; l_i[i] = 0.f;
        #pragma unroll
        for (int j = 0; j < 4; j++) O[i][j] = 0.f;
    }

    const int nPrefix = Pp / 64;
    const int nBlk = nPrefix + qt + 1;

    for (int jb = 0; jb < nBlk; jb++) {
        __syncthreads();

        const float* kr; const float* vr;
        if (jb < nPrefix) {
            size_t base = ((size_t)(b*Hh + h)*Pp + jb*64 + lr) * Dd;
            kr = cache_k + base;
            vr = cache_v + base;
        } else {
            size_t base = ((size_t)(b*Tt + (jb - nPrefix)*64 + lr))*C3 + h*Dd;
            kr = qkv + base + Cc;
            vr = qkv + base + 2*Cc;
        }
        #pragma unroll
        for (int u = 0; u < 4; u++) {
            int d4 = (lq + 4*u) * 4;
            float4 kv = *(const float4*)&kr[d4];
            sKP[(d4+0)*FP + lr] = kv.x;
            sKP[(d4+1)*FP + lr] = kv.y;
            sKP[(d4+2)*FP + lr] = kv.z;
            sKP[(d4+3)*FP + lr] = kv.w;
            *(float4*)&sV[lr*FP + d4] = *(const float4*)&vr[d4];
        }
        __syncthreads();

        float S[4][4];
        #pragma unroll
        for (int i = 0; i < 4; i++)
            #pragma unroll
            for (int j = 0; j < 4; j++) S[i][j] = 0.f;

        #pragma unroll 8
        for (int d = 0; d < 64; d++) {
            float4 qv = *(const float4*)&sQt[d*FP + ty4];
            float4 kv = *(const float4*)&sKP[d*FP + tx4];
            float qa[4] = {qv.x, qv.y, qv.z, qv.w};
            float ka[4] = {kv.x, kv.y, kv.z, kv.w};
            #pragma unroll
            for (int i = 0; i < 4; i++)
                #pragma unroll
                for (int j = 0; j < 4; j++)
                    S[i][j] = fmaf(qa[i], ka[j], S[i][j]);
        }

        if (jb == nBlk - 1) {
            #pragma unroll
            for (int i = 0; i < 4; i++)
                #pragma unroll
                for (int j = 0; j < 4; j++)
                    if (tx4 + j > ty4 + i) S[i][j] = -1e30f;
        }

        float alpha[4];
        #pragma unroll
        for (int i = 0; i < 4; i++) {
            float rm = fmaxf(fmaxf(S[i][0], S[i][1]), fmaxf(S[i][2], S[i][3]));
            #pragma unroll
            for (int msk = 1; msk < 16; msk <<= 1)
                rm = fmaxf(rm, __shfl_xor_sync(0xffffffffu, rm, msk));
            float mn = fmaxf(m_i[i], rm);
            alpha[i] = __expf(m_i[i] - mn);
            float rs = 0.f;
            #pragma unroll
            for (int j = 0; j < 4; j++) {
                float p = __expf(S[i][j] - mn);
                S[i][j] = p;
                rs += p;
            }
            #pragma unroll
            for (int msk = 1; msk < 16; msk <<= 1)
                rs += __shfl_xor_sync(0xffffffffu, rs, msk);
            l_i[i] = l_i[i] * alpha[i] + rs;
            m_i[i] = mn;
            #pragma unroll
            for (int j = 0; j < 4; j++) O[i][j] *= alpha[i];
        }

        __syncthreads();

        #pragma unroll
        for (int i = 0; i < 4; i++)
            *(float4*)&sKP[(ty4+i)*FP + tx4] =
                make_float4(S[i][0], S[i][1], S[i][2], S[i][3]);
        __syncthreads();

        #pragma unroll 8
        for (int kk = 0; kk < 64; kk++) {
            float4 vv = *(const float4*)&sV[kk*FP + tx4];
            float va[4] = {vv.x, vv.y, vv.z, vv.w};
            float pa[4];
            #pragma unroll
            for (int i = 0; i < 4; i++) pa[i] = sKP[(ty4+i)*FP + kk];
            #pragma unroll
            for (int i = 0; i < 4; i++)
                #pragma unroll
                for (int j = 0; j < 4; j++)
                    O[i][j] = fmaf(pa[i], va[j], O[i][j]);
        }
    }

    #pragma unroll
    for (int i = 0; i < 4; i++) {
        float inv = 1.f / l_i[i];
        float4 o = make_float4(O[i][0]*inv, O[i][1]*inv, O[i][2]*inv, O[i][3]*inv);
        *(float4*)&y[((size_t)(b*Tt + q0 + ty4 + i))*Cc + h*Dd + tx4] = o;
    }
}

// ---------------------------------------------------------------------------
// Launch
// ---------------------------------------------------------------------------
extern "C" void kernel_launch(void* const* d_in, const int* in_sizes, int n_in,
                              void* d_out, int out_size)
{
    const float* x       = (const float*)d_in[0];
    const float* W_attn  = (const float*)d_in[1];
    const float* W_proj  = (const float*)d_in[2];
    const float* cache_k = (const float*)d_in[3];
    const float* cache_v = (const float*)d_in[4];
    float* out = (float*)d_out;

    float *qkv_p = nullptr, *y_p = nullptr;
    __nv_bfloat16 *xhi, *xlo, *yhi, *ylo, *wahi, *walo, *wphi, *wplo;
    cudaGetSymbolAddress((void**)&qkv_p, g_qkv);
    cudaGetSymbolAddress((void**)&y_p, g_y);
    cudaGetSymbolAddress((void**)&xhi, g_xhi);
    cudaGetSymbolAddress((void**)&xlo, g_xlo);
    cudaGetSymbolAddress((void**)&yhi, g_yhi);
    cudaGetSymbolAddress((void**)&ylo, g_ylo);
    cudaGetSymbolAddress((void**)&wahi, g_wahi);
    cudaGetSymbolAddress((void**)&walo, g_walo);
    cudaGetSymbolAddress((void**)&wphi, g_wphi);
    cudaGetSymbolAddress((void**)&wplo, g_wplo);

    const int smem_flash = 3 * 64 * FP * (int)sizeof(float);
    cudaFuncSetAttribute(flash_kernel,
                         cudaFuncAttributeMaxDynamicSharedMemorySize, smem_flash);
    cudaFuncSetAttribute(gemm_mma,
                         cudaFuncAttributeMaxDynamicSharedMemorySize, GEMM_SMEM);

    // 0) fp32 -> bf16 hi/lo splits (+ W transposes)
    {
        int n4 = MM * Cc / 4;
        split_kernel<<<(n4 + 255) / 256, 256>>>(x, xhi, xlo, n4);
    }
    wsplit_t_kernel<<<dim3(C3/32, Cc/32), dim3(32, 8)>>>(W_attn, wahi, walo, Cc, C3);
    wsplit_t_kernel<<<dim3(Cc/32, Cc/32), dim3(32, 8)>>>(W_proj, wphi, wplo, Cc, Cc);

    // 1) qkv = x @ W_attn  (tensor cores, bf16-split)
    gemm_mma<<<dim3(C3/128, MM/128), 256, GEMM_SMEM>>>(xhi, xlo, wahi, walo,
                                                       qkv_p, MM, C3, Cc);
    // 2) flash attention over prefix + causal self
    flash_kernel<<<dim3(Tt/64, Hh, Bb), 256, smem_flash>>>(qkv_p, cache_k,
                                                           cache_v, y_p);
    // 3) split y, then out = y @ W_proj (tensor cores)
    {
        int n4 = MM * Cc / 4;
        split_kernel<<<(n4 + 255) / 256, 256>>>(y_p, yhi, ylo, n4);
    }
    gemm_mma<<<dim3(Cc/128, MM/128), 256, GEMM_SMEM>>>(yhi, ylo, wphi, wplo,
                                                       out, MM, Cc, Cc);
}

// round 6
// speedup vs baseline: 2.9849x; 2.3439x over previous
#include <cuda_runtime.h>
#include <cuda_bf16.h>
#include <cstdint>

// Problem constants (fixed by the reference)
#define Bb 2
#define Tt 2048
#define Cc 1024
#define Hh 16
#define Dd 64
#define Pp 2048
#define C3 3072
#define MM (Bb*Tt)   // 4096 rows

// ---------------------------------------------------------------------------
// Scratch (device globals — no runtime allocation allowed)
// ---------------------------------------------------------------------------
__device__ float g_qkv[(size_t)MM * C3];                 // [B*T, 3C]
__device__ __nv_bfloat16 g_xhi[(size_t)MM * Cc];
__device__ __nv_bfloat16 g_xlo[(size_t)MM * Cc];
__device__ __nv_bfloat16 g_yhi[(size_t)MM * Cc];         // attention out, split
__device__ __nv_bfloat16 g_ylo[(size_t)MM * Cc];
__device__ __nv_bfloat16 g_wahi[(size_t)C3 * Cc];        // W_attn^T [3072][1024]
__device__ __nv_bfloat16 g_walo[(size_t)C3 * Cc];
__device__ __nv_bfloat16 g_wphi[(size_t)Cc * Cc];        // W_proj^T [1024][1024]
__device__ __nv_bfloat16 g_wplo[(size_t)Cc * Cc];

// ---------------------------------------------------------------------------
// PTX helpers: mma.sync / ldmatrix / cp.async (all valid on plain sm_103)
// ---------------------------------------------------------------------------
__device__ __forceinline__ uint32_t smem_u32(const void* p) {
    uint32_t a;
    asm("{ .reg .u64 t; cvta.to.shared.u64 t, %1; cvt.u32.u64 %0, t; }"
        : "=r"(a) : "l"(p));
    return a;
}
__device__ __forceinline__ void ldsm_x4(uint32_t* r, uint32_t addr) {
    asm volatile("ldmatrix.sync.aligned.m8n8.x4.shared.b16 {%0,%1,%2,%3}, [%4];"
        : "=r"(r[0]), "=r"(r[1]), "=r"(r[2]), "=r"(r[3]) : "r"(addr));
}
__device__ __forceinline__ void ldsm_x4_t(uint32_t* r, uint32_t addr) {
    asm volatile("ldmatrix.sync.aligned.m8n8.x4.trans.shared.b16 {%0,%1,%2,%3}, [%4];"
        : "=r"(r[0]), "=r"(r[1]), "=r"(r[2]), "=r"(r[3]) : "r"(addr));
}
__device__ __forceinline__ void mma16816(float* d, const uint32_t* a,
                                         uint32_t b0, uint32_t b1) {
    asm volatile(
        "mma.sync.aligned.m16n8k16.row.col.f32.bf16.bf16.f32 "
        "{%0,%1,%2,%3}, {%4,%5,%6,%7}, {%8,%9}, {%0,%1,%2,%3};"
        : "+f"(d[0]), "+f"(d[1]), "+f"(d[2]), "+f"(d[3])
        : "r"(a[0]), "r"(a[1]), "r"(a[2]), "r"(a[3]), "r"(b0), "r"(b1));
}
__device__ __forceinline__ void cp16(uint32_t dst, const void* src) {
    asm volatile("cp.async.cg.shared.global [%0], [%1], 16;"
                 :: "r"(dst), "l"(src) : "memory");
}
#define CP_COMMIT() asm volatile("cp.async.commit_group;" ::: "memory")
#define CP_WAIT(n)  asm volatile("cp.async.wait_group %0;" :: "n"(n) : "memory")

// pack two floats -> bf16x2 (x in low half, y in high half)
__device__ __forceinline__ uint32_t cvt2(float x, float y) {
    uint32_t r;
    asm("cvt.rn.bf16x2.f32 %0, %1, %2;" : "=r"(r) : "f"(y), "f"(x));
    return r;
}
// split (x,y) into bf16x2 hi and bf16x2 lo (residual)
__device__ __forceinline__ void split2(float x, float y, uint32_t& h, uint32_t& l) {
    h = cvt2(x, y);
    float hx = __uint_as_float(h << 16);
    float hy = __uint_as_float(h & 0xFFFF0000u);
    l = cvt2(x - hx, y - hy);
}

// ---------------------------------------------------------------------------
// fp32 -> (bf16 hi, bf16 lo) split, elementwise (x activations)
// ---------------------------------------------------------------------------
__global__ __launch_bounds__(256)
void split_kernel(const float* __restrict__ in, __nv_bfloat16* __restrict__ hi,
                  __nv_bfloat16* __restrict__ lo, int n4)
{
    int i = blockIdx.x * blockDim.x + threadIdx.x;
    if (i >= n4) return;
    float4 v = ((const float4*)in)[i];
    uint32_t h0, l0, h1, l1;
    split2(v.x, v.y, h0, l0);
    split2(v.z, v.w, h1, l1);
    ((uint2*)hi)[i] = make_uint2(h0, h1);
    ((uint2*)lo)[i] = make_uint2(l0, l1);
}

// ---------------------------------------------------------------------------
// W [KW,NW] fp32 -> transposed bf16 hi/lo [NW,KW] (K-major)
// ---------------------------------------------------------------------------
__global__ __launch_bounds__(256)
void wsplit_t_kernel(const float* __restrict__ W, __nv_bfloat16* __restrict__ hi,
                     __nv_bfloat16* __restrict__ lo, int KW, int NW)
{
    __shared__ float t[32][33];
    const int n0 = blockIdx.x * 32, k0 = blockIdx.y * 32;
    const int tx = threadIdx.x, ty = threadIdx.y;
    #pragma unroll
    for (int r = 0; r < 4; r++)
        t[ty + 8*r][tx] = W[(size_t)(k0 + ty + 8*r) * NW + n0 + tx];
    __syncthreads();
    #pragma unroll
    for (int r = 0; r < 4; r++) {
        int n = ty + 8*r;
        float v = t[tx][n];
        __nv_bfloat16 h = __float2bfloat16_rn(v);
        __nv_bfloat16 l = __float2bfloat16_rn(v - __bfloat162float(h));
        size_t o = (size_t)(n0 + n) * KW + k0 + tx;
        hi[o] = h;
        lo[o] = l;
    }
}

// ---------------------------------------------------------------------------
// Tensor-core GEMM (mma.sync bf16-split) — unchanged from R5 (passing)
// ---------------------------------------------------------------------------
#define PLANE 16384
#define STAGE (4 * PLANE)
#define GEMM_SMEM (2 * STAGE)    // 131072 B

__device__ __forceinline__ void load_stage(
    const __nv_bfloat16* __restrict__ Ahi, const __nv_bfloat16* __restrict__ Alo,
    const __nv_bfloat16* __restrict__ Bhi, const __nv_bfloat16* __restrict__ Blo,
    int bm, int bn, int K, int kt, uint32_t so, int tid)
{
    const __nv_bfloat16* srcs[4] = {Ahi, Alo, Bhi, Blo};
    #pragma unroll
    for (int p = 0; p < 4; p++) {
        const __nv_bfloat16* src = srcs[p];
        const int rb = (p < 2) ? bm : bn;
        #pragma unroll
        for (int i = 0; i < 4; i++) {
            int idx = i * 256 + tid;
            int row = idx >> 3, c = idx & 7;
            uint32_t dst = so + p * PLANE + row * 128 + ((c ^ (row & 7)) << 4);
            cp16(dst, src + (size_t)(rb + row) * K + kt * 64 + c * 8);
        }
    }
}

__global__ __launch_bounds__(256, 1)
void gemm_mma(const __nv_bfloat16* __restrict__ Ahi, const __nv_bfloat16* __restrict__ Alo,
              const __nv_bfloat16* __restrict__ Bhi, const __nv_bfloat16* __restrict__ Blo,
              float* __restrict__ Cm, int M, int N, int K)
{
    extern __shared__ char smem[];
    const uint32_t sb = smem_u32(smem);
    const int tid = threadIdx.x;
    const int wid = tid >> 5, lane = tid & 31;
    const int bn = blockIdx.x * 128, bm = blockIdx.y * 128;
    const int m0 = (wid >> 2) * 64;
    const int n0 = (wid & 3) * 32;

    float acc[4][4][4];
    #pragma unroll
    for (int mt = 0; mt < 4; mt++)
        #pragma unroll
        for (int nt = 0; nt < 4; nt++)
            #pragma unroll
            for (int j = 0; j < 4; j++) acc[mt][nt][j] = 0.f;

    const int KT = K / 64;
    load_stage(Ahi, Alo, Bhi, Blo, bm, bn, K, 0, sb, tid);
    CP_COMMIT();

    const int a_rh = (lane >> 3) & 1;
    const int a_kh = lane >> 4;
    const int b_nh = lane >> 4;
    const int b_kh = (lane >> 3) & 1;
    const int l7 = lane & 7;

    for (int kt = 0; kt < KT; kt++) {
        const int s = kt & 1;
        if (kt + 1 < KT) {
            load_stage(Ahi, Alo, Bhi, Blo, bm, bn, K, kt + 1, sb + (s ^ 1) * STAGE, tid);
            CP_COMMIT();
            CP_WAIT(1);
        } else {
            CP_WAIT(0);
        }
        __syncthreads();

        const uint32_t Ah = sb + s * STAGE;
        const uint32_t Al = Ah + PLANE;
        const uint32_t Bh = Ah + 2 * PLANE;
        const uint32_t Bl = Ah + 3 * PLANE;

        #pragma unroll
        for (int ks = 0; ks < 4; ks++) {
            uint32_t ah[4][4], al[4][4], bh[4][2], bl[4][2];
            #pragma unroll
            for (int mt = 0; mt < 4; mt++) {
                int r = m0 + mt * 16 + a_rh * 8 + l7;
                int kc = ks * 2 + a_kh;
                uint32_t off = (uint32_t)(r * 128 + ((kc ^ (r & 7)) << 4));
                ldsm_x4(ah[mt], Ah + off);
                ldsm_x4(al[mt], Al + off);
            }
            #pragma unroll
            for (int nt2 = 0; nt2 < 2; nt2++) {
                int rn = n0 + nt2 * 16 + b_nh * 8 + l7;
                int kc = ks * 2 + b_kh;
                uint32_t off = (uint32_t)(rn * 128 + ((kc ^ (rn & 7)) << 4));
                uint32_t t0[4], t1[4];
                ldsm_x4(t0, Bh + off);
                ldsm_x4(t1, Bl + off);
                bh[nt2*2][0] = t0[0]; bh[nt2*2][1] = t0[1];
                bh[nt2*2+1][0] = t0[2]; bh[nt2*2+1][1] = t0[3];
                bl[nt2*2][0] = t1[0]; bl[nt2*2][1] = t1[1];
                bl[nt2*2+1][0] = t1[2]; bl[nt2*2+1][1] = t1[3];
            }
            #pragma unroll
            for (int mt = 0; mt < 4; mt++)
                #pragma unroll
                for (int nt = 0; nt < 4; nt++) {
                    mma16816(acc[mt][nt], ah[mt], bh[nt][0], bh[nt][1]);
                    mma16816(acc[mt][nt], ah[mt], bl[nt][0], bl[nt][1]);
                    mma16816(acc[mt][nt], al[mt], bh[nt][0], bh[nt][1]);
                }
        }
        __syncthreads();
    }

    const int g = lane >> 2, q = lane & 3;
    #pragma unroll
    for (int mt = 0; mt < 4; mt++) {
        #pragma unroll
        for (int nt = 0; nt < 4; nt++) {
            size_t row = (size_t)(bm + m0 + mt * 16 + g);
            size_t col = (size_t)(bn + n0 + nt * 8 + q * 2);
            *(float2*)&Cm[row * N + col] = make_float2(acc[mt][nt][0], acc[mt][nt][1]);
            *(float2*)&Cm[(row + 8) * N + col] = make_float2(acc[mt][nt][2], acc[mt][nt][3]);
        }
    }
}

// ---------------------------------------------------------------------------
// Tensor-core flash attention. One CTA = (b, h, 128-query tile), 8 warps.
// Each warp owns 16 query rows. S = QK^T and O += PV via bf16-split mma.sync.
// exp2-domain softmax (log2e folded into Q scale). Writes yhi/ylo directly.
// ---------------------------------------------------------------------------
#define QSC (0.125f * 1.44269504088896340736f)

__global__ __launch_bounds__(256)
void flash_mma(const float* __restrict__ qkv,
               const float* __restrict__ cache_k,
               const float* __restrict__ cache_v,
               __nv_bfloat16* __restrict__ yhi,
               __nv_bfloat16* __restrict__ ylo)
{
    __shared__ __align__(16) uint8_t sK[16384];   // hi: [0,8K), lo: [8K,16K)
    __shared__ __align__(16) uint8_t sV[16384];
    const uint32_t sKa = smem_u32(sK), sVa = smem_u32(sV);

    const int tid = threadIdx.x;
    const int wid = tid >> 5, lane = tid & 31;
    const int g = lane >> 2, qd = lane & 3, l7 = lane & 7;
    const int qt = (int)gridDim.x - 1 - (int)blockIdx.x;   // big tiles first
    const int h = blockIdx.y, b = blockIdx.z;
    const int q0 = qt * 128;
    const int wm0 = wid * 16;

    // ---- Q fragments hi/lo, pre-scaled by (1/8)*log2(e) ----
    uint32_t qh[4][4], ql[4][4];
    {
        const float* qb = qkv + ((size_t)(b*Tt + q0 + wm0))*C3 + h*Dd;
        #pragma unroll
        for (int kt = 0; kt < 4; kt++)
            #pragma unroll
            for (int f = 0; f < 4; f++) {
                int r = g + (f & 1) * 8;
                int c = kt*16 + 2*qd + (f >> 1) * 8;
                float2 v = *(const float2*)(qb + (size_t)r*C3 + c);
                split2(v.x * QSC, v.y * QSC, qh[kt][f], ql[kt][f]);
            }
    }

    float O[8][4];
    #pragma unroll
    for (int nt = 0; nt < 8; nt++)
        #pragma unroll
        for (int e = 0; e < 4; e++) O[nt][e] = 0.f;
    float m_i[2] = {-1e30f, -1e30f}, l_i[2] = {0.f, 0.f};

    const int nBlk = 32 + 2*qt + 2;

    // prefetch mapping: thread -> (row 0..63, 16-float column chunk)
    const int pr = tid >> 2;
    const int pc = (tid & 3) * 16;

    float4 pk[4], pv[4];
    {
        size_t base = (((size_t)(b*Hh + h))*Pp + pr)*Dd + pc;
        #pragma unroll
        for (int i = 0; i < 4; i++) {
            pk[i] = *(const float4*)(cache_k + base + i*4);
            pv[i] = *(const float4*)(cache_v + base + i*4);
        }
    }

    for (int jb = 0; jb < nBlk; jb++) {
        const bool self = jb >= 32;
        const int kbase = (jb - 32) * 64;

        // ---- store prefetched K/V block (split fp32 -> bf16 hi/lo, swizzled)
        #pragma unroll
        for (int i = 0; i < 2; i++) {
            uint32_t h0,l0,h1,l1,h2,l2,h3,l3;
            split2(pk[2*i].x,   pk[2*i].y,   h0, l0);
            split2(pk[2*i].z,   pk[2*i].w,   h1, l1);
            split2(pk[2*i+1].x, pk[2*i+1].y, h2, l2);
            split2(pk[2*i+1].z, pk[2*i+1].w, h3, l3);
            int ch = 2*(tid & 3) + i;
            uint32_t off = pr*128 + ((ch ^ (pr & 7)) << 4);
            *(uint4*)(sK + off)        = make_uint4(h0,h1,h2,h3);
            *(uint4*)(sK + 8192 + off) = make_uint4(l0,l1,l2,l3);
            split2(pv[2*i].x,   pv[2*i].y,   h0, l0);
            split2(pv[2*i].z,   pv[2*i].w,   h1, l1);
            split2(pv[2*i+1].x, pv[2*i+1].y, h2, l2);
            split2(pv[2*i+1].z, pv[2*i+1].w, h3, l3);
            *(uint4*)(sV + off)        = make_uint4(h0,h1,h2,h3);
            *(uint4*)(sV + 8192 + off) = make_uint4(l0,l1,l2,l3);
        }
        __syncthreads();

        // ---- prefetch next block into registers (overlaps MMAs below)
        if (jb + 1 < nBlk) {
            const float *kr_, *vr_;
            if (jb + 1 < 32) {
                size_t base = (((size_t)(b*Hh + h))*Pp + (jb+1)*64 + pr)*Dd + pc;
                kr_ = cache_k + base;
                vr_ = cache_v + base;
            } else {
                size_t base = ((size_t)(b*Tt + (jb+1-32)*64 + pr))*C3 + h*Dd + pc;
                kr_ = qkv + base + Cc;
                vr_ = qkv + base + 2*Cc;
            }
            #pragma unroll
            for (int i = 0; i < 4; i++) {
                pk[i] = *(const float4*)(kr_ + i*4);
                pv[i] = *(const float4*)(vr_ + i*4);
            }
        }

        // warp fully above diagonal? (all keys of block > all rows of warp)
        const bool active = !(self && kbase > q0 + wm0 + 15);
        if (active) {
            // ---- S = Q K^T (3-way split, fp32 accum)
            float Sf[8][4];
            #pragma unroll
            for (int nt = 0; nt < 8; nt++)
                #pragma unroll
                for (int e = 0; e < 4; e++) Sf[nt][e] = 0.f;

            #pragma unroll
            for (int ks = 0; ks < 4; ks++) {
                uint32_t kbh[8][2], kbl[8][2];
                #pragma unroll
                for (int p = 0; p < 4; p++) {
                    int row = p*16 + (lane >> 4)*8 + l7;
                    int ch = ks*2 + ((lane >> 3) & 1);
                    uint32_t off = row*128 + ((ch ^ (row & 7)) << 4);
                    uint32_t t0[4], t1[4];
                    ldsm_x4(t0, sKa + off);
                    ldsm_x4(t1, sKa + 8192 + off);
                    kbh[2*p][0]=t0[0]; kbh[2*p][1]=t0[1];
                    kbh[2*p+1][0]=t0[2]; kbh[2*p+1][1]=t0[3];
                    kbl[2*p][0]=t1[0]; kbl[2*p][1]=t1[1];
                    kbl[2*p+1][0]=t1[2]; kbl[2*p+1][1]=t1[3];
                }
                #pragma unroll
                for (int nt = 0; nt < 8; nt++) {
                    mma16816(Sf[nt], qh[ks], kbh[nt][0], kbh[nt][1]);
                    mma16816(Sf[nt], qh[ks], kbl[nt][0], kbl[nt][1]);
                    mma16816(Sf[nt], ql[ks], kbh[nt][0], kbh[nt][1]);
                }
            }

            // ---- causal mask (diagonal-straddling self blocks only)
            if (self && kbase + 63 > q0 + wm0) {
                #pragma unroll
                for (int nt = 0; nt < 8; nt++)
                    #pragma unroll
                    for (int e = 0; e < 4; e++) {
                        int r_ = q0 + wm0 + g + (e >> 1)*8;
                        int n_ = kbase + nt*8 + 2*qd + (e & 1);
                        if (n_ > r_) Sf[nt][e] = -1e30f;
                    }
            }

            // ---- online softmax (exp2 domain), rows rr=0 (g), rr=1 (g+8)
            float alpha[2];
            #pragma unroll
            for (int rr = 0; rr < 2; rr++) {
                float mx = -1e30f;
                #pragma unroll
                for (int nt = 0; nt < 8; nt++)
                    mx = fmaxf(mx, fmaxf(Sf[nt][2*rr], Sf[nt][2*rr+1]));
                mx = fmaxf(mx, __shfl_xor_sync(0xffffffffu, mx, 1));
                mx = fmaxf(mx, __shfl_xor_sync(0xffffffffu, mx, 2));
                float mn = fmaxf(m_i[rr], mx);
                alpha[rr] = exp2f(m_i[rr] - mn);
                m_i[rr] = mn;
                float rs = 0.f;
                #pragma unroll
                for (int nt = 0; nt < 8; nt++) {
                    float p0 = exp2f(Sf[nt][2*rr]   - mn);
                    float p1 = exp2f(Sf[nt][2*rr+1] - mn);
                    Sf[nt][2*rr] = p0; Sf[nt][2*rr+1] = p1;
                    rs += p0 + p1;
                }
                rs += __shfl_xor_sync(0xffffffffu, rs, 1);
                rs += __shfl_xor_sync(0xffffffffu, rs, 2);
                l_i[rr] = l_i[rr] * alpha[rr] + rs;
            }
            #pragma unroll
            for (int nt = 0; nt < 8; nt++)
                #pragma unroll
                for (int e = 0; e < 4; e++) O[nt][e] *= alpha[e >> 1];

            // ---- repack P (S-frags) into A-frags, split hi/lo
            uint32_t ph[4][4], pl[4][4];
            #pragma unroll
            for (int j = 0; j < 4; j++) {
                split2(Sf[2*j][0],   Sf[2*j][1],   ph[j][0], pl[j][0]);
                split2(Sf[2*j][2],   Sf[2*j][3],   ph[j][1], pl[j][1]);
                split2(Sf[2*j+1][0], Sf[2*j+1][1], ph[j][2], pl[j][2]);
                split2(Sf[2*j+1][2], Sf[2*j+1][3], ph[j][3], pl[j][3]);
            }

            // ---- O += P V (V via trans ldmatrix: smem [key][d] = [k][n])
            #pragma unroll
            for (int kt = 0; kt < 4; kt++) {
                uint32_t vbh[8][2], vbl[8][2];
                #pragma unroll
                for (int p = 0; p < 4; p++) {
                    int row = kt*16 + ((lane >> 3) & 1)*8 + l7;
                    int ch = p*2 + (lane >> 4);
                    uint32_t off = row*128 + ((ch ^ (row & 7)) << 4);
                    uint32_t t0[4], t1[4];
                    ldsm_x4_t(t0, sVa + off);
                    ldsm_x4_t(t1, sVa + 8192 + off);
                    vbh[2*p][0]=t0[0]; vbh[2*p][1]=t0[1];
                    vbh[2*p+1][0]=t0[2]; vbh[2*p+1][1]=t0[3];
                    vbl[2*p][0]=t1[0]; vbl[2*p][1]=t1[1];
                    vbl[2*p+1][0]=t1[2]; vbl[2*p+1][1]=t1[3];
                }
                #pragma unroll
                for (int nt = 0; nt < 8; nt++) {
                    mma16816(O[nt], ph[kt], vbh[nt][0], vbh[nt][1]);
                    mma16816(O[nt], ph[kt], vbl[nt][0], vbl[nt][1]);
                    mma16816(O[nt], pl[kt], vbh[nt][0], vbh[nt][1]);
                }
            }
        }
        __syncthreads();
    }

    // ---- normalize + write split y (ready for proj GEMM)
    #pragma unroll
    for (int rr = 0; rr < 2; rr++) {
        float inv = 1.f / l_i[rr];
        size_t row = (size_t)(b*Tt + q0 + wm0 + g + rr*8);
        #pragma unroll
        for (int nt = 0; nt < 8; nt++) {
            float a = O[nt][2*rr] * inv;
            float c = O[nt][2*rr+1] * inv;
            uint32_t hh, ll;
            split2(a, c, hh, ll);
            size_t idx = (row*Cc + h*Dd + nt*8 + 2*qd) >> 1;
            ((uint32_t*)yhi)[idx] = hh;
            ((uint32_t*)ylo)[idx] = ll;
        }
    }
}

// ---------------------------------------------------------------------------
// Launch
// ---------------------------------------------------------------------------
extern "C" void kernel_launch(void* const* d_in, const int* in_sizes, int n_in,
                              void* d_out, int out_size)
{
    const float* x       = (const float*)d_in[0];
    const float* W_attn  = (const float*)d_in[1];
    const float* W_proj  = (const float*)d_in[2];
    const float* cache_k = (const float*)d_in[3];
    const float* cache_v = (const float*)d_in[4];
    float* out = (float*)d_out;

    float* qkv_p = nullptr;
    __nv_bfloat16 *xhi, *xlo, *yhi, *ylo, *wahi, *walo, *wphi, *wplo;
    cudaGetSymbolAddress((void**)&qkv_p, g_qkv);
    cudaGetSymbolAddress((void**)&xhi, g_xhi);
    cudaGetSymbolAddress((void**)&xlo, g_xlo);
    cudaGetSymbolAddress((void**)&yhi, g_yhi);
    cudaGetSymbolAddress((void**)&ylo, g_ylo);
    cudaGetSymbolAddress((void**)&wahi, g_wahi);
    cudaGetSymbolAddress((void**)&walo, g_walo);
    cudaGetSymbolAddress((void**)&wphi, g_wphi);
    cudaGetSymbolAddress((void**)&wplo, g_wplo);

    cudaFuncSetAttribute(gemm_mma,
                         cudaFuncAttributeMaxDynamicSharedMemorySize, GEMM_SMEM);

    // 0) fp32 -> bf16 hi/lo splits (+ W transposes)
    {
        int n4 = MM * Cc / 4;
        split_kernel<<<(n4 + 255) / 256, 256>>>(x, xhi, xlo, n4);
    }
    wsplit_t_kernel<<<dim3(C3/32, Cc/32), dim3(32, 8)>>>(W_attn, wahi, walo, Cc, C3);
    wsplit_t_kernel<<<dim3(Cc/32, Cc/32), dim3(32, 8)>>>(W_proj, wphi, wplo, Cc, Cc);

    // 1) qkv = x @ W_attn  (tensor cores, bf16-split)
    gemm_mma<<<dim3(C3/128, MM/128), 256, GEMM_SMEM>>>(xhi, xlo, wahi, walo,
                                                       qkv_p, MM, C3, Cc);
    // 2) tensor-core flash attention (writes split y directly)
    flash_mma<<<dim3(Tt/128, Hh, Bb), 256>>>(qkv_p, cache_k, cache_v, yhi, ylo);

    // 3) out = y @ W_proj (tensor cores)
    gemm_mma<<<dim3(Cc/128, MM/128), 256, GEMM_SMEM>>>(yhi, ylo, wphi, wplo,
                                                       out, MM, Cc, Cc);
}